// round 3
// baseline (speedup 1.0000x reference)
#include <cuda_runtime.h>
#include <cuda_fp16.h>

#define N_NODES 100000
#define N_EDGES 1600000
#define D_IN    256
#define HF      128     // N_HEADS * D_OUT
#define NEG_SLOPE 0.2f

#define SCAN_BLK 256
#define N_SCAN_BLOCKS ((N_NODES + SCAN_BLK - 1) / SCAN_BLK)   // 391

// ---------------- scratch (device globals: allocation-free) ----------------
__device__ __half g_ft2[(size_t)N_NODES * HF];       // 25.6 MB fp16 features (gather payload)
__device__ float  g_elf[N_NODES * 4];                // per-node left logits [N][4]
__device__ float  g_erf[N_NODES * 4];                // per-node right logits [N][4]
__device__ unsigned long long g_wt2[(D_IN / 2) * HF];// W repacked as k-pairs, [k2][c]
__device__ int g_counts[N_NODES];
__device__ int g_offsets[N_NODES];
__device__ int g_cursor[N_NODES];
__device__ int g_bsums[N_SCAN_BLOCKS];
__device__ int g_src_sorted[N_EDGES];

// ---------------- f32x2 helpers (Blackwell packed fp32) ----------------
__device__ __forceinline__ unsigned long long pack2(float lo, float hi) {
    unsigned long long r;
    asm("mov.b64 %0, {%1, %2};" : "=l"(r)
        : "r"(__float_as_uint(lo)), "r"(__float_as_uint(hi)));
    return r;
}
__device__ __forceinline__ void unpack2(unsigned long long v, float& lo, float& hi) {
    unsigned int a, b;
    asm("mov.b64 {%0, %1}, %2;" : "=r"(a), "=r"(b) : "l"(v));
    lo = __uint_as_float(a);
    hi = __uint_as_float(b);
}
__device__ __forceinline__ unsigned long long ffma2(unsigned long long a,
                                                    unsigned long long b,
                                                    unsigned long long c) {
    unsigned long long d;
    asm("fma.rn.f32x2 %0, %1, %2, %3;" : "=l"(d) : "l"(a), "l"(b), "l"(c));
    return d;
}

// ---------------- 0. zero counters ----------------
__global__ void zero_kernel() {
    int i = blockIdx.x * blockDim.x + threadIdx.x;
    if (i < N_NODES) { g_counts[i] = 0; g_cursor[i] = 0; }
}

// ---------------- 1. repack W: wt2[k2*128+c] = (W[c][2k2], W[c][2k2+1]) ----------------
__global__ void wtrans_kernel(const float* __restrict__ w) {
    int idx = blockIdx.x * blockDim.x + threadIdx.x;
    if (idx < (D_IN / 2) * HF) {
        int c  = idx & (HF - 1);
        int k2 = idx >> 7;
        g_wt2[idx] = pack2(w[c * D_IN + 2 * k2], w[c * D_IN + 2 * k2 + 1]);
    }
}

// ---------------- 2. GEMM + fused el/er epilogue ----------------
// ft[n][c] = sum_k x[n][k]*W[c][k]  (f32x2 packed over k)
// warp owns one head's 32 cols for its 8 rows -> el/er via warp reduction.
// ft stored ONLY as fp16 (gather payload); el/er stay exact fp32.
#define TILE_ROWS 32
__global__ void __launch_bounds__(512) gemm_kernel(const float* __restrict__ x,
                                                   const float* __restrict__ al,
                                                   const float* __restrict__ ar) {
    __shared__ float xs[TILE_ROWS * D_IN];   // 32 KB
    int tid  = threadIdx.x;
    int c    = tid & 127;      // output column (0..127)
    int rg   = tid >> 7;       // row group (0..3), 8 rows each
    int lane = tid & 31;
    int h    = (tid >> 5) & 3; // head owned by this warp (c == h*32 + lane')

    int row0 = blockIdx.x * TILE_ROWS;

    const float4* xg  = (const float4*)(x + (size_t)row0 * D_IN);
    float4*       xs4 = (float4*)xs;
#pragma unroll
    for (int i = 0; i < 4; i++) xs4[tid + 512 * i] = __ldg(&xg[tid + 512 * i]);
    __syncthreads();

    unsigned long long acc[8];
#pragma unroll
    for (int r = 0; r < 8; r++) acc[r] = 0ULL;

    const unsigned long long* wp = g_wt2 + c;
    const float* xr = xs + (rg * 8) * D_IN;

#pragma unroll 4
    for (int k2 = 0; k2 < D_IN / 2; k2++) {
        unsigned long long w = __ldg(wp + (size_t)k2 * HF);
#pragma unroll
        for (int r = 0; r < 8; r++) {
            unsigned long long xv =
                *(const unsigned long long*)(xr + r * D_IN + 2 * k2);
            acc[r] = ffma2(xv, w, acc[r]);
        }
    }

    float alc = __ldg(al + c);
    float arc = __ldg(ar + c);

#pragma unroll
    for (int r = 0; r < 8; r++) {
        float lo, hi; unpack2(acc[r], lo, hi);
        float o = lo + hi;
        int  node = row0 + rg * 8 + r;
        g_ft2[(size_t)node * HF + c] = __float2half(o);
        // fused attention logits: sum over this warp's 32 cols == full head
        float pl = o * alc;
        float pr = o * arc;
#pragma unroll
        for (int off = 16; off; off >>= 1) {
            pl += __shfl_xor_sync(0xffffffffu, pl, off);
            pr += __shfl_xor_sync(0xffffffffu, pr, off);
        }
        if (lane == 0) {
            g_elf[node * 4 + h] = pl;
            g_erf[node * 4 + h] = pr;
        }
    }
}

// ---------------- 3. histogram of dst ----------------
__global__ void hist_kernel(const int* __restrict__ dst) {
    int i = blockIdx.x * blockDim.x + threadIdx.x;
    if (i < N_EDGES) atomicAdd(&g_counts[dst[i]], 1);
}

// ---------------- 4. two-level exclusive scan ----------------
__global__ void scanA_kernel() {
    __shared__ int sm[SCAN_BLK];
    int t = threadIdx.x;
    int i = blockIdx.x * SCAN_BLK + t;
    int v = (i < N_NODES) ? g_counts[i] : 0;
    sm[t] = v; __syncthreads();
    for (int off = 1; off < SCAN_BLK; off <<= 1) {
        int u = (t >= off) ? sm[t - off] : 0;
        __syncthreads();
        sm[t] += u;
        __syncthreads();
    }
    if (i < N_NODES) g_offsets[i] = sm[t] - v;
    if (t == SCAN_BLK - 1) g_bsums[blockIdx.x] = sm[t];
}

__global__ void __launch_bounds__(512) scanB_kernel() {
    __shared__ int sm[512];
    int t = threadIdx.x;
    int v = (t < N_SCAN_BLOCKS) ? g_bsums[t] : 0;
    sm[t] = v; __syncthreads();
    for (int off = 1; off < 512; off <<= 1) {
        int u = (t >= off) ? sm[t - off] : 0;
        __syncthreads();
        sm[t] += u;
        __syncthreads();
    }
    if (t < N_SCAN_BLOCKS) g_bsums[t] = sm[t] - v;
}

__global__ void scanC_kernel() {
    int i = blockIdx.x * blockDim.x + threadIdx.x;
    if (i < N_NODES) g_offsets[i] += g_bsums[i >> 8];
}

// ---------------- 5. scatter edges into dst-sorted order ----------------
__global__ void scatter_kernel(const int* __restrict__ src,
                               const int* __restrict__ dst) {
    int i = blockIdx.x * blockDim.x + threadIdx.x;
    if (i < N_EDGES) {
        int d   = dst[i];
        int pos = g_offsets[d] + atomicAdd(&g_cursor[d], 1);
        g_src_sorted[pos] = src[i];
    }
}

// ---------------- 6. aggregate: warp per dst node ----------------
// Lane i owns head h=i>>3, output floats [4i..4i+3]. Each lane computes its own
// exp -> per-head denominator needs NO cross-lane reduction (every lane of a
// head accumulates the identical full sum). Gather payload is fp16 (256B/edge).
__global__ void __launch_bounds__(256) agg_kernel(float* __restrict__ out) {
    int n    = (blockIdx.x * blockDim.x + threadIdx.x) >> 5;
    int lane = threadIdx.x & 31;
    if (n >= N_NODES) return;
    int h = lane >> 3;

    int base = __ldg(&g_offsets[n]);
    int deg  = __ldg(&g_counts[n]);

    const float4* el4p = (const float4*)g_elf;
    float4 er4 = ((const float4*)g_erf)[n];
    float erh = (h == 0) ? er4.x : (h == 1) ? er4.y : (h == 2) ? er4.z : er4.w;

    const uint2* ftu = (const uint2*)g_ft2;   // 8B = 4 halfs per lane

    float a0 = 0.f, a1 = 0.f, a2 = 0.f, a3 = 0.f;
    float d = 0.f;

    for (int j0 = 0; j0 < deg; j0 += 32) {
        int j = j0 + lane;
        int s = (j < deg) ? __ldg(&g_src_sorted[base + j]) : 0;
        int m = min(32, deg - j0);
        for (int jj = 0; jj < m; jj++) {
            int sv = __shfl_sync(0xffffffffu, s, jj);
            float4 el4 = __ldg(&el4p[sv]);                       // broadcast 16B
            float t = ((h == 0) ? el4.x : (h == 1) ? el4.y
                      : (h == 2) ? el4.z : el4.w) + erh;
            t = (t > 0.f) ? t : NEG_SLOPE * t;
            float w = __expf(t);
            d += w;
            uint2 v = __ldg(&ftu[(size_t)sv * 32 + lane]);       // 256B/edge coalesced
            float2 f01 = __half22float2(*(const __half2*)&v.x);
            float2 f23 = __half22float2(*(const __half2*)&v.y);
            a0 += w * f01.x;
            a1 += w * f01.y;
            a2 += w * f23.x;
            a3 += w * f23.y;
        }
    }

    float inv = (deg > 0) ? 1.f / d : 0.f;
    float4 o = make_float4(a0 * inv, a1 * inv, a2 * inv, a3 * inv);
    ((float4*)out)[(size_t)n * 32 + lane] = o;
}

// ---------------- launch ----------------
extern "C" void kernel_launch(void* const* d_in, const int* in_sizes, int n_in,
                              void* d_out, int out_size) {
    const float* x    = (const float*)d_in[0];
    const float* fc_w = (const float*)d_in[1];
    const float* al   = (const float*)d_in[2];
    const float* ar   = (const float*)d_in[3];
    const int*   src  = (const int*)d_in[4];
    const int*   dst  = (const int*)d_in[5];
    float*       out  = (float*)d_out;

    zero_kernel<<<(N_NODES + 255) / 256, 256>>>();
    wtrans_kernel<<<((D_IN / 2) * HF + 255) / 256, 256>>>(fc_w);
    gemm_kernel<<<N_NODES / TILE_ROWS, 512>>>(x, al, ar);            // 3125 blocks
    hist_kernel<<<(N_EDGES + 255) / 256, 256>>>(dst);
    scanA_kernel<<<N_SCAN_BLOCKS, SCAN_BLK>>>();
    scanB_kernel<<<1, 512>>>();
    scanC_kernel<<<(N_NODES + 255) / 256, 256>>>();
    scatter_kernel<<<(N_EDGES + 255) / 256, 256>>>(src, dst);
    agg_kernel<<<(N_NODES * 32) / 256, 256>>>(out);                  // 12500 blocks
}

// round 7
// speedup vs baseline: 1.5470x; 1.5470x over previous
#include <cuda_runtime.h>
#include <cuda_fp16.h>

#define N_NODES 100000
#define N_EDGES 1600000
#define D_IN    256
#define HF      128     // N_HEADS * D_OUT
#define NEG_SLOPE 0.2f

#define SCAN_BLK 256
#define N_SCAN_BLOCKS ((N_NODES + SCAN_BLK - 1) / SCAN_BLK)   // 391

// ---------------- scratch (device globals: allocation-free) ----------------
__device__ __half g_ft2[(size_t)N_NODES * HF];       // 25.6 MB fp16 features (gather payload)
__device__ float  g_elf[N_NODES * 4];                // per-node left logits [N][4]
__device__ float  g_erf[N_NODES * 4];                // per-node right logits [N][4]
__device__ unsigned long long g_wt2[(D_IN / 2) * HF];// W repacked as k-pairs, [k2][c]
__device__ int    g_counts[N_NODES];
__device__ int    g_offsets[N_NODES];
__device__ int    g_cursor[N_NODES];
__device__ int    g_bsums[N_SCAN_BLOCKS];
__device__ int    g_src_sorted[N_EDGES];
__device__ float4 g_w4[N_EDGES];                     // per-edge softmax weights (4 heads)

// ---------------- f32x2 helpers (Blackwell packed fp32) ----------------
__device__ __forceinline__ unsigned long long pack2(float lo, float hi) {
    unsigned long long r;
    asm("mov.b64 %0, {%1, %2};" : "=l"(r)
        : "r"(__float_as_uint(lo)), "r"(__float_as_uint(hi)));
    return r;
}
__device__ __forceinline__ void unpack2(unsigned long long v, float& lo, float& hi) {
    unsigned int a, b;
    asm("mov.b64 {%0, %1}, %2;" : "=r"(a), "=r"(b) : "l"(v));
    lo = __uint_as_float(a);
    hi = __uint_as_float(b);
}
__device__ __forceinline__ unsigned long long ffma2(unsigned long long a,
                                                    unsigned long long b,
                                                    unsigned long long c) {
    unsigned long long d;
    asm("fma.rn.f32x2 %0, %1, %2, %3;" : "=l"(d) : "l"(a), "l"(b), "l"(c));
    return d;
}

// ---------------- 0. zero counters ----------------
__global__ void zero_kernel() {
    int i = blockIdx.x * blockDim.x + threadIdx.x;
    if (i < N_NODES) { g_counts[i] = 0; g_cursor[i] = 0; }
}

// ---------------- 1. repack W: wt2[k2*128+c] = (W[c][2k2], W[c][2k2+1]) ----------------
__global__ void wtrans_kernel(const float* __restrict__ w) {
    int idx = blockIdx.x * blockDim.x + threadIdx.x;
    if (idx < (D_IN / 2) * HF) {
        int c  = idx & (HF - 1);
        int k2 = idx >> 7;
        g_wt2[idx] = pack2(w[c * D_IN + 2 * k2], w[c * D_IN + 2 * k2 + 1]);
    }
}

// ---------------- 2. GEMM + fused el/er epilogue ----------------
// 128 threads/block, tile = 32 rows x 128 cols.
// Thread: 8 rows (rg = warp) x 4 cols (c_j = lane + 32j). Warp spans all 128
// cols of its 8 rows, head j reduced across the 32 lanes.
#define TILE_ROWS 32
__global__ void __launch_bounds__(128) gemm_kernel(const float* __restrict__ x,
                                                   const float* __restrict__ al,
                                                   const float* __restrict__ ar) {
    __shared__ float xs[TILE_ROWS * D_IN];   // 32 KB
    int tid  = threadIdx.x;
    int lane = tid & 31;
    int rg   = tid >> 5;        // warp id = row group (8 rows)

    int row0 = blockIdx.x * TILE_ROWS;

    // coalesced float4 copy of the x tile (32 rows x 256 cols), 16 per thread
    const float4* xg  = (const float4*)(x + (size_t)row0 * D_IN);
    float4*       xs4 = (float4*)xs;
#pragma unroll
    for (int i = 0; i < 16; i++) xs4[tid + 128 * i] = __ldg(&xg[tid + 128 * i]);
    __syncthreads();

    unsigned long long acc[8][4];
#pragma unroll
    for (int r = 0; r < 8; r++)
#pragma unroll
        for (int j = 0; j < 4; j++) acc[r][j] = 0ULL;

    const unsigned long long* wp = g_wt2 + lane;
    const float* xr = xs + (rg * 8) * D_IN;

#pragma unroll 2
    for (int k2 = 0; k2 < D_IN / 2; k2++) {
        unsigned long long w[4];
#pragma unroll
        for (int j = 0; j < 4; j++)
            w[j] = __ldg(wp + (size_t)k2 * HF + 32 * j);   // coalesced, L1-resident
        unsigned long long xv[8];
#pragma unroll
        for (int r = 0; r < 8; r++)
            xv[r] = *(const unsigned long long*)(xr + r * D_IN + 2 * k2); // LDS.64 bcast
#pragma unroll
        for (int r = 0; r < 8; r++)
#pragma unroll
            for (int j = 0; j < 4; j++)
                acc[r][j] = ffma2(xv[r], w[j], acc[r][j]);
    }

    float alc[4], arc[4];
#pragma unroll
    for (int j = 0; j < 4; j++) {
        alc[j] = __ldg(al + lane + 32 * j);
        arc[j] = __ldg(ar + lane + 32 * j);
    }

#pragma unroll
    for (int r = 0; r < 8; r++) {
        int node = row0 + rg * 8 + r;
        float pl[4], pr[4];
#pragma unroll
        for (int j = 0; j < 4; j++) {
            float lo, hi; unpack2(acc[r][j], lo, hi);
            float o = lo + hi;
            g_ft2[(size_t)node * HF + lane + 32 * j] = __float2half(o);
            pl[j] = o * alc[j];
            pr[j] = o * arc[j];
        }
#pragma unroll
        for (int off = 16; off; off >>= 1) {
#pragma unroll
            for (int j = 0; j < 4; j++) {
                pl[j] += __shfl_xor_sync(0xffffffffu, pl[j], off);
                pr[j] += __shfl_xor_sync(0xffffffffu, pr[j], off);
            }
        }
        if (lane == 0) {
#pragma unroll
            for (int j = 0; j < 4; j++) {
                g_elf[node * 4 + j] = pl[j];
                g_erf[node * 4 + j] = pr[j];
            }
        }
    }
}

// ---------------- 3. histogram of dst ----------------
__global__ void hist_kernel(const int* __restrict__ dst) {
    int i = blockIdx.x * blockDim.x + threadIdx.x;
    if (i < N_EDGES) atomicAdd(&g_counts[dst[i]], 1);
}

// ---------------- 4. two-level exclusive scan ----------------
__global__ void scanA_kernel() {
    __shared__ int sm[SCAN_BLK];
    int t = threadIdx.x;
    int i = blockIdx.x * SCAN_BLK + t;
    int v = (i < N_NODES) ? g_counts[i] : 0;
    sm[t] = v; __syncthreads();
    for (int off = 1; off < SCAN_BLK; off <<= 1) {
        int u = (t >= off) ? sm[t - off] : 0;
        __syncthreads();
        sm[t] += u;
        __syncthreads();
    }
    if (i < N_NODES) g_offsets[i] = sm[t] - v;
    if (t == SCAN_BLK - 1) g_bsums[blockIdx.x] = sm[t];
}

__global__ void __launch_bounds__(512) scanB_kernel() {
    __shared__ int sm[512];
    int t = threadIdx.x;
    int v = (t < N_SCAN_BLOCKS) ? g_bsums[t] : 0;
    sm[t] = v; __syncthreads();
    for (int off = 1; off < 512; off <<= 1) {
        int u = (t >= off) ? sm[t - off] : 0;
        __syncthreads();
        sm[t] += u;
        __syncthreads();
    }
    if (t < N_SCAN_BLOCKS) g_bsums[t] = sm[t] - v;
}

__global__ void scanC_kernel() {
    int i = blockIdx.x * blockDim.x + threadIdx.x;
    if (i < N_NODES) g_offsets[i] += g_bsums[i >> 8];
}

// ---------------- 5. scatter + fused edge softmax weights ----------------
// Computes w[e][h] = exp(leaky(el[src][h] + er[dst][h])) once per edge (6.4M
// MUFU total, overlapped with the scatter's atomics/stores) and writes it at
// the dst-sorted position. Agg then needs no exp and no shfl.
__global__ void scatter_kernel(const int* __restrict__ src,
                               const int* __restrict__ dst) {
    int i = blockIdx.x * blockDim.x + threadIdx.x;
    if (i >= N_EDGES) return;
    int s = src[i];
    int d = dst[i];
    int pos = g_offsets[d] + atomicAdd(&g_cursor[d], 1);
    g_src_sorted[pos] = s;

    float4 el = __ldg(&((const float4*)g_elf)[s]);   // L2-resident (1.6MB)
    float4 er = __ldg(&((const float4*)g_erf)[d]);
    float t0 = el.x + er.x; t0 = (t0 > 0.f) ? t0 : NEG_SLOPE * t0;
    float t1 = el.y + er.y; t1 = (t1 > 0.f) ? t1 : NEG_SLOPE * t1;
    float t2 = el.z + er.z; t2 = (t2 > 0.f) ? t2 : NEG_SLOPE * t2;
    float t3 = el.w + er.w; t3 = (t3 > 0.f) ? t3 : NEG_SLOPE * t3;
    g_w4[pos] = make_float4(__expf(t0), __expf(t1), __expf(t2), __expf(t3));
}

// ---------------- 6. aggregate: warp per dst node, exp-free, shfl-free ----------------
// Lane owns head h = lane>>3 and output floats [4*lane .. 4*lane+3].
// Per edge: broadcast LDG of s, 4B LDG of this head's weight, 8B fp16 gather,
// 4 FFMA + 1 FADD. Denominator needs no reduction (8 lanes of a head
// accumulate identical sums).
__global__ void __launch_bounds__(256) agg_kernel(float* __restrict__ out) {
    int n    = (blockIdx.x * blockDim.x + threadIdx.x) >> 5;
    int lane = threadIdx.x & 31;
    if (n >= N_NODES) return;
    int h = lane >> 3;

    int base = __ldg(&g_offsets[n]);
    int deg  = __ldg(&g_counts[n]);

    const float* wh  = ((const float*)g_w4) + h;     // w[e][h]
    const uint2* ftu = (const uint2*)g_ft2;          // 8B = 4 halfs per lane

    float a0 = 0.f, a1 = 0.f, a2 = 0.f, a3 = 0.f;
    float d = 0.f;

    for (int j = 0; j < deg; j++) {
        int   sv = __ldg(&g_src_sorted[base + j]);           // broadcast 4B
        float w  = __ldg(wh + (size_t)(base + j) * 4);       // 1 wavefront (4 addrs)
        uint2 v  = __ldg(&ftu[(size_t)sv * 32 + lane]);      // 256B/edge coalesced
        float2 f01 = __half22float2(*(const __half2*)&v.x);
        float2 f23 = __half22float2(*(const __half2*)&v.y);
        d  += w;
        a0 += w * f01.x;
        a1 += w * f01.y;
        a2 += w * f23.x;
        a3 += w * f23.y;
    }

    float inv = (deg > 0) ? 1.f / d : 0.f;
    float4 o = make_float4(a0 * inv, a1 * inv, a2 * inv, a3 * inv);
    ((float4*)out)[(size_t)n * 32 + lane] = o;
}

// ---------------- launch ----------------
extern "C" void kernel_launch(void* const* d_in, const int* in_sizes, int n_in,
                              void* d_out, int out_size) {
    const float* x    = (const float*)d_in[0];
    const float* fc_w = (const float*)d_in[1];
    const float* al   = (const float*)d_in[2];
    const float* ar   = (const float*)d_in[3];
    const int*   src  = (const int*)d_in[4];
    const int*   dst  = (const int*)d_in[5];
    float*       out  = (float*)d_out;

    zero_kernel<<<(N_NODES + 255) / 256, 256>>>();
    wtrans_kernel<<<((D_IN / 2) * HF + 255) / 256, 256>>>(fc_w);
    gemm_kernel<<<N_NODES / TILE_ROWS, 128>>>(x, al, ar);            // 3125 blocks
    hist_kernel<<<(N_EDGES + 255) / 256, 256>>>(dst);
    scanA_kernel<<<N_SCAN_BLOCKS, SCAN_BLK>>>();
    scanB_kernel<<<1, 512>>>();
    scanC_kernel<<<(N_NODES + 255) / 256, 256>>>();
    scatter_kernel<<<(N_EDGES + 255) / 256, 256>>>(src, dst);
    agg_kernel<<<(N_NODES * 32) / 256, 256>>>(out);                  // 12500 blocks
}

// round 10
// speedup vs baseline: 3.3648x; 2.1751x over previous
#include <cuda_runtime.h>
#include <cuda_fp16.h>

#define N_NODES 100000
#define N_EDGES 1600000
#define D_IN    256
#define HF      128     // N_HEADS * D_OUT
#define NEG_SLOPE 0.2f

#define SCAN_BLK 256
#define N_SCAN_BLOCKS ((N_NODES + SCAN_BLK - 1) / SCAN_BLK)   // 391

#define GEMM_BM 128
#define GEMM_GRID ((N_NODES + GEMM_BM - 1) / GEMM_BM)         // 782

// ---------------- scratch (device globals: allocation-free) ----------------
__device__ __half g_ft2[(size_t)N_NODES * HF];       // 25.6 MB fp16 features
__device__ __half g_wh[HF * D_IN];                   // W fp16, [c][k] (k contiguous)
__device__ float  g_elf[N_NODES * 4];
__device__ float  g_erf[N_NODES * 4];
__device__ int    g_counts[N_NODES];
__device__ int    g_offsets[N_NODES];
__device__ int    g_cursor[N_NODES];
__device__ int    g_bsums[N_SCAN_BLOCKS];
__device__ int    g_src_sorted[N_EDGES];
__device__ float4 g_w4[N_EDGES];                     // per-edge softmax weights

// ---------------- 0. zero counters ----------------
__global__ void zero_kernel() {
    int i = blockIdx.x * blockDim.x + threadIdx.x;
    if (i < N_NODES) { g_counts[i] = 0; g_cursor[i] = 0; }
}

// ---------------- 1. W fp32 -> fp16 (layout unchanged: [c][k]) ----------------
__global__ void wtrans_kernel(const float* __restrict__ w) {
    int i = blockIdx.x * blockDim.x + threadIdx.x;
    if (i < HF * D_IN) g_wh[i] = __float2half(w[i]);
}

// ---------------- 2. HMMA GEMM: ft = x @ W^T, fp16 in / fp32 acc / fp16 out --
// Block: 128 rows x 128 cols x K=256 (full K in smem). 256 threads = 8 warps,
// warp grid 4(m) x 2(n); warp tile 32x64 = 2x8 m16n8k16 mma tiles.
// smem: A 128x256 fp16 (64KB) + B(=W) 128x256 fp16 (64KB), both row-stride
// 512B with 16B-chunk XOR swizzle: chunk' = chunk ^ (row & 7)  -> conflict-free
// ldmatrix AND conflict-free fill stores.
// Fragment mapping note: mma m16n8k16 B frag wants {B[k][n]} with thread(T):
// n = T/4, k = 2*(T%4)+e (+8 for b1). Plain (non-trans) ldmatrix on k-contiguous
// [n][k] rows delivers exactly that, so BOTH operands use ldmatrix.x4 non-trans.
__global__ void __launch_bounds__(256) gemm_kernel(const float* __restrict__ x) {
    extern __shared__ char smem[];
    char* As = smem;            // 65536 bytes
    char* Bs = smem + 65536;    // 65536 bytes

    int tid  = threadIdx.x;
    int lane = tid & 31;
    int wid  = tid >> 5;
    int wm   = wid & 3;         // warp row group (32 rows)
    int wn   = wid >> 2;        // warp col group (64 cols)
    int row0 = blockIdx.x * GEMM_BM;

    // ---- fill A: x fp32 -> fp16, swizzled. thread = one 16B chunk (8 halves)
#pragma unroll
    for (int it = 0; it < 16; it++) {
        int cid = tid + 256 * it;          // 0..4095
        int row = cid >> 5;                // 0..127
        int ck  = cid & 31;                // 16B chunk within row
        int grow = row0 + row;
        float4 f0, f1;
        if (grow < N_NODES) {
            const float4* xp = (const float4*)(x + (size_t)grow * D_IN + ck * 8);
            f0 = __ldg(xp); f1 = __ldg(xp + 1);
        } else {
            f0 = make_float4(0.f, 0.f, 0.f, 0.f); f1 = f0;
        }
        __half2 h0 = __floats2half2_rn(f0.x, f0.y);
        __half2 h1 = __floats2half2_rn(f0.z, f0.w);
        __half2 h2 = __floats2half2_rn(f1.x, f1.y);
        __half2 h3 = __floats2half2_rn(f1.z, f1.w);
        uint4 v = make_uint4(*(unsigned*)&h0, *(unsigned*)&h1,
                             *(unsigned*)&h2, *(unsigned*)&h3);
        *(uint4*)(As + row * 512 + ((ck ^ (row & 7)) << 4)) = v;
    }
    // ---- fill B: g_wh fp16 straight copy, swizzled
#pragma unroll
    for (int it = 0; it < 16; it++) {
        int cid = tid + 256 * it;
        int row = cid >> 5;
        int ck  = cid & 31;
        uint4 v = __ldg((const uint4*)(g_wh + row * D_IN + ck * 8));
        *(uint4*)(Bs + row * 512 + ((ck ^ (row & 7)) << 4)) = v;
    }
    __syncthreads();

    unsigned aBase = (unsigned)__cvta_generic_to_shared(As);
    unsigned bBase = (unsigned)__cvta_generic_to_shared(Bs);

    float c[2][8][4];
#pragma unroll
    for (int mt = 0; mt < 2; mt++)
#pragma unroll
        for (int nt = 0; nt < 8; nt++)
#pragma unroll
            for (int e = 0; e < 4; e++) c[mt][nt][e] = 0.f;

    // lane-invariant pieces of the ldmatrix addresses
    int aRowL = wm * 32 + (lane & 7) + ((lane >> 3) & 1) * 8;   // + mt*16
    int aKbL  = (lane >> 4) * 16;                               // + kb
    int bRowL = wn * 64 + (lane & 7) + (lane >> 4) * 8;         // + nt2*16
    int bKbL  = ((lane >> 3) & 1) * 16;                         // + kb

#pragma unroll
    for (int ks = 0; ks < 16; ks++) {
        int kb = ks * 32;                  // byte offset of this k16 step
        unsigned a[2][4];
#pragma unroll
        for (int mt = 0; mt < 2; mt++) {
            int r = aRowL + mt * 16;
            int kbyte = kb + aKbL;
            unsigned addr = aBase + r * 512 + ((((kbyte >> 4) ^ (r & 7)) << 4));
            asm volatile(
                "ldmatrix.sync.aligned.m8n8.x4.shared.b16 {%0,%1,%2,%3}, [%4];"
                : "=r"(a[mt][0]), "=r"(a[mt][1]), "=r"(a[mt][2]), "=r"(a[mt][3])
                : "r"(addr));
        }
        unsigned b[8][2];
#pragma unroll
        for (int nt2 = 0; nt2 < 4; nt2++) {
            int r = bRowL + nt2 * 16;
            int kbyte = kb + bKbL;
            unsigned addr = bBase + r * 512 + ((((kbyte >> 4) ^ (r & 7)) << 4));
            unsigned r0, r1, r2, r3;
            asm volatile(
                "ldmatrix.sync.aligned.m8n8.x4.shared.b16 {%0,%1,%2,%3}, [%4];"
                : "=r"(r0), "=r"(r1), "=r"(r2), "=r"(r3)
                : "r"(addr));
            b[nt2 * 2 + 0][0] = r0; b[nt2 * 2 + 0][1] = r1;
            b[nt2 * 2 + 1][0] = r2; b[nt2 * 2 + 1][1] = r3;
        }
#pragma unroll
        for (int mt = 0; mt < 2; mt++)
#pragma unroll
            for (int nt = 0; nt < 8; nt++) {
                asm volatile(
                    "mma.sync.aligned.m16n8k16.row.col.f32.f16.f16.f32 "
                    "{%0,%1,%2,%3}, {%4,%5,%6,%7}, {%8,%9}, {%0,%1,%2,%3};"
                    : "+f"(c[mt][nt][0]), "+f"(c[mt][nt][1]),
                      "+f"(c[mt][nt][2]), "+f"(c[mt][nt][3])
                    : "r"(a[mt][0]), "r"(a[mt][1]), "r"(a[mt][2]), "r"(a[mt][3]),
                      "r"(b[nt][0]), "r"(b[nt][1]));
            }
    }

    // ---- epilogue: fp32 acc -> fp16 ft
    int gid = lane >> 2, tig = lane & 3;
#pragma unroll
    for (int mt = 0; mt < 2; mt++) {
        int r0 = row0 + wm * 32 + mt * 16 + gid;
        int r1 = r0 + 8;
#pragma unroll
        for (int nt = 0; nt < 8; nt++) {
            int col = wn * 64 + nt * 8 + tig * 2;
            if (r0 < N_NODES) {
                __half2 h = __floats2half2_rn(c[mt][nt][0], c[mt][nt][1]);
                *(__half2*)(g_ft2 + (size_t)r0 * HF + col) = h;
            }
            if (r1 < N_NODES) {
                __half2 h = __floats2half2_rn(c[mt][nt][2], c[mt][nt][3]);
                *(__half2*)(g_ft2 + (size_t)r1 * HF + col) = h;
            }
        }
    }
}

// ---------------- 3. per-node logits el/er from fp16 ft (L2-resident) -------
__global__ void elr_kernel(const float* __restrict__ al, const float* __restrict__ ar) {
    int n    = (blockIdx.x * blockDim.x + threadIdx.x) >> 5;
    int lane = threadIdx.x & 31;
    if (n >= N_NODES) return;
    uint2 v = __ldg((const uint2*)(g_ft2 + (size_t)n * HF) + lane);  // 4 halves
    float2 f01 = __half22float2(*(const __half2*)&v.x);
    float2 f23 = __half22float2(*(const __half2*)&v.y);
    float4 alv = __ldg((const float4*)al + lane);
    float4 arv = __ldg((const float4*)ar + lane);
    float l = f01.x * alv.x + f01.y * alv.y + f23.x * alv.z + f23.y * alv.w;
    float r = f01.x * arv.x + f01.y * arv.y + f23.x * arv.z + f23.y * arv.w;
#pragma unroll
    for (int o = 4; o; o >>= 1) {         // reduce within 8-lane head group
        l += __shfl_xor_sync(0xffffffffu, l, o);
        r += __shfl_xor_sync(0xffffffffu, r, o);
    }
    if ((lane & 7) == 0) {
        int h = lane >> 3;
        g_elf[n * 4 + h] = l;
        g_erf[n * 4 + h] = r;
    }
}

// ---------------- 4. histogram of dst ----------------
__global__ void hist_kernel(const int* __restrict__ dst) {
    int i = blockIdx.x * blockDim.x + threadIdx.x;
    if (i < N_EDGES) atomicAdd(&g_counts[dst[i]], 1);
}

// ---------------- 5. two-level exclusive scan ----------------
__global__ void scanA_kernel() {
    __shared__ int sm[SCAN_BLK];
    int t = threadIdx.x;
    int i = blockIdx.x * SCAN_BLK + t;
    int v = (i < N_NODES) ? g_counts[i] : 0;
    sm[t] = v; __syncthreads();
    for (int off = 1; off < SCAN_BLK; off <<= 1) {
        int u = (t >= off) ? sm[t - off] : 0;
        __syncthreads();
        sm[t] += u;
        __syncthreads();
    }
    if (i < N_NODES) g_offsets[i] = sm[t] - v;
    if (t == SCAN_BLK - 1) g_bsums[blockIdx.x] = sm[t];
}

__global__ void __launch_bounds__(512) scanB_kernel() {
    __shared__ int sm[512];
    int t = threadIdx.x;
    int v = (t < N_SCAN_BLOCKS) ? g_bsums[t] : 0;
    sm[t] = v; __syncthreads();
    for (int off = 1; off < 512; off <<= 1) {
        int u = (t >= off) ? sm[t - off] : 0;
        __syncthreads();
        sm[t] += u;
        __syncthreads();
    }
    if (t < N_SCAN_BLOCKS) g_bsums[t] = sm[t] - v;
}

__global__ void scanC_kernel() {
    int i = blockIdx.x * blockDim.x + threadIdx.x;
    if (i < N_NODES) g_offsets[i] += g_bsums[i >> 8];
}

// ---------------- 6. scatter + fused edge softmax weights ----------------
__global__ void scatter_kernel(const int* __restrict__ src,
                               const int* __restrict__ dst) {
    int i = blockIdx.x * blockDim.x + threadIdx.x;
    if (i >= N_EDGES) return;
    int s = src[i];
    int d = dst[i];
    int pos = g_offsets[d] + atomicAdd(&g_cursor[d], 1);
    g_src_sorted[pos] = s;

    float4 el = __ldg(&((const float4*)g_elf)[s]);
    float4 er = __ldg(&((const float4*)g_erf)[d]);
    float t0 = el.x + er.x; t0 = (t0 > 0.f) ? t0 : NEG_SLOPE * t0;
    float t1 = el.y + er.y; t1 = (t1 > 0.f) ? t1 : NEG_SLOPE * t1;
    float t2 = el.z + er.z; t2 = (t2 > 0.f) ? t2 : NEG_SLOPE * t2;
    float t3 = el.w + er.w; t3 = (t3 > 0.f) ? t3 : NEG_SLOPE * t3;
    g_w4[pos] = make_float4(__expf(t0), __expf(t1), __expf(t2), __expf(t3));
}

// ---------------- 7. aggregate: warp per dst node, prefetched ----------------
__global__ void __launch_bounds__(256) agg_kernel(float* __restrict__ out) {
    int n    = (blockIdx.x * blockDim.x + threadIdx.x) >> 5;
    int lane = threadIdx.x & 31;
    if (n >= N_NODES) return;
    int h = lane >> 3;

    int base = __ldg(&g_offsets[n]);
    int deg  = __ldg(&g_counts[n]);

    const float* wh  = ((const float*)g_w4) + h;
    const uint2* ftu = (const uint2*)g_ft2;

    float a0 = 0.f, a1 = 0.f, a2 = 0.f, a3 = 0.f;
    float d = 0.f;

    int   sv_n = 0;
    float w_n  = 0.f;
    if (deg > 0) {
        sv_n = __ldg(&g_src_sorted[base]);
        w_n  = __ldg(wh + (size_t)base * 4);
    }
    for (int j = 0; j < deg; j++) {
        int   sv = sv_n;
        float w  = w_n;
        if (j + 1 < deg) {                               // prefetch next edge
            sv_n = __ldg(&g_src_sorted[base + j + 1]);
            w_n  = __ldg(wh + (size_t)(base + j + 1) * 4);
        }
        uint2 v = __ldg(&ftu[(size_t)sv * 32 + lane]);   // 256B/edge, L2
        float2 f01 = __half22float2(*(const __half2*)&v.x);
        float2 f23 = __half22float2(*(const __half2*)&v.y);
        d  += w;
        a0 += w * f01.x;
        a1 += w * f01.y;
        a2 += w * f23.x;
        a3 += w * f23.y;
    }

    float inv = (deg > 0) ? 1.f / d : 0.f;
    float4 o = make_float4(a0 * inv, a1 * inv, a2 * inv, a3 * inv);
    ((float4*)out)[(size_t)n * 32 + lane] = o;
}

// ---------------- launch ----------------
extern "C" void kernel_launch(void* const* d_in, const int* in_sizes, int n_in,
                              void* d_out, int out_size) {
    const float* x    = (const float*)d_in[0];
    const float* fc_w = (const float*)d_in[1];
    const float* al   = (const float*)d_in[2];
    const float* ar   = (const float*)d_in[3];
    const int*   src  = (const int*)d_in[4];
    const int*   dst  = (const int*)d_in[5];
    float*       out  = (float*)d_out;

    static bool attr_set = false;
    if (!attr_set) {
        cudaFuncSetAttribute(gemm_kernel,
                             cudaFuncAttributeMaxDynamicSharedMemorySize, 131072);
        attr_set = true;
    }

    zero_kernel<<<(N_NODES + 255) / 256, 256>>>();
    wtrans_kernel<<<(HF * D_IN + 255) / 256, 256>>>(fc_w);
    gemm_kernel<<<GEMM_GRID, 256, 131072>>>(x);                      // 782 blocks
    elr_kernel<<<(N_NODES * 32 + 255) / 256, 256>>>(al, ar);
    hist_kernel<<<(N_EDGES + 255) / 256, 256>>>(dst);
    scanA_kernel<<<N_SCAN_BLOCKS, SCAN_BLK>>>();
    scanB_kernel<<<1, 512>>>();
    scanC_kernel<<<(N_NODES + 255) / 256, 256>>>();
    scatter_kernel<<<(N_EDGES + 255) / 256, 256>>>(src, dst);
    agg_kernel<<<(N_NODES * 32) / 256, 256>>>(out);                  // 12500 blocks
}

// round 12
// speedup vs baseline: 3.6883x; 1.0961x over previous
#include <cuda_runtime.h>
#include <cuda_fp16.h>

#define N_NODES 100000
#define N_EDGES 1600000
#define D_IN    256
#define HF      128     // N_HEADS * D_OUT
#define NEG_SLOPE 0.2f

#define SCAN_BLK 256
#define N_SCAN_BLOCKS ((N_NODES + SCAN_BLK - 1) / SCAN_BLK)   // 391

#define GEMM_BM 128
#define GEMM_GRID ((N_NODES + GEMM_BM - 1) / GEMM_BM)         // 782

// ---------------- scratch (device globals: allocation-free) ----------------
__device__ __half g_ft2[(size_t)N_NODES * HF];       // 25.6 MB fp16 features
__device__ __half g_wh[HF * D_IN];                   // W fp16, [c][k]
__device__ float  g_elf[N_NODES * 4];
__device__ float  g_erf[N_NODES * 4];
__device__ int    g_counts[N_NODES];
__device__ int    g_offsets[N_NODES];
__device__ int    g_cursor[N_NODES];
__device__ int    g_bsums[N_SCAN_BLOCKS];
__device__ int    g_src_sorted[N_EDGES + 4];         // +pad: prefetch overrun safe
__device__ float4 g_w4[N_EDGES + 4];                 // per-edge softmax weights

// ---------------- 0. zero counters ----------------
__global__ void zero_kernel() {
    int i = blockIdx.x * blockDim.x + threadIdx.x;
    if (i < N_NODES) { g_counts[i] = 0; g_cursor[i] = 0; }
}

// ---------------- 1. W fp32 -> fp16 ----------------
__global__ void wtrans_kernel(const float* __restrict__ w) {
    int i = blockIdx.x * blockDim.x + threadIdx.x;
    if (i < HF * D_IN) g_wh[i] = __float2half(w[i]);
}

// ---------------- 2. HMMA GEMM + fused el/er epilogue ----------------
// Block 128x128xK256, 8 warps (4m x 2n), warp tile 32x64 = 2x8 m16n8k16.
// Epilogue: head h = cols [32h,32h+32) lives entirely in warp wn = h>>1, so
// el/er reduce with 2 shfl_xor over the 4-lane quad; lane tig==0 stores.
__global__ void __launch_bounds__(256) gemm_kernel(const float* __restrict__ x,
                                                   const float* __restrict__ al,
                                                   const float* __restrict__ ar) {
    extern __shared__ char smem[];
    char* As = smem;            // 65536 bytes
    char* Bs = smem + 65536;    // 65536 bytes

    int tid  = threadIdx.x;
    int lane = tid & 31;
    int wid  = tid >> 5;
    int wm   = wid & 3;         // warp row group (32 rows)
    int wn   = wid >> 2;        // warp col group (64 cols)
    int row0 = blockIdx.x * GEMM_BM;

    // ---- fill A: x fp32 -> fp16, swizzled (16B chunk per thread-iter)
#pragma unroll
    for (int it = 0; it < 16; it++) {
        int cid = tid + 256 * it;          // 0..4095
        int row = cid >> 5;
        int ck  = cid & 31;
        int grow = row0 + row;
        float4 f0, f1;
        if (grow < N_NODES) {
            const float4* xp = (const float4*)(x + (size_t)grow * D_IN + ck * 8);
            f0 = __ldg(xp); f1 = __ldg(xp + 1);
        } else {
            f0 = make_float4(0.f, 0.f, 0.f, 0.f); f1 = f0;
        }
        __half2 h0 = __floats2half2_rn(f0.x, f0.y);
        __half2 h1 = __floats2half2_rn(f0.z, f0.w);
        __half2 h2 = __floats2half2_rn(f1.x, f1.y);
        __half2 h3 = __floats2half2_rn(f1.z, f1.w);
        uint4 v = make_uint4(*(unsigned*)&h0, *(unsigned*)&h1,
                             *(unsigned*)&h2, *(unsigned*)&h3);
        *(uint4*)(As + row * 512 + ((ck ^ (row & 7)) << 4)) = v;
    }
    // ---- fill B: g_wh fp16 straight copy, swizzled
#pragma unroll
    for (int it = 0; it < 16; it++) {
        int cid = tid + 256 * it;
        int row = cid >> 5;
        int ck  = cid & 31;
        uint4 v = __ldg((const uint4*)(g_wh + row * D_IN + ck * 8));
        *(uint4*)(Bs + row * 512 + ((ck ^ (row & 7)) << 4)) = v;
    }
    __syncthreads();

    unsigned aBase = (unsigned)__cvta_generic_to_shared(As);
    unsigned bBase = (unsigned)__cvta_generic_to_shared(Bs);

    float c[2][8][4];
#pragma unroll
    for (int mt = 0; mt < 2; mt++)
#pragma unroll
        for (int nt = 0; nt < 8; nt++)
#pragma unroll
            for (int e = 0; e < 4; e++) c[mt][nt][e] = 0.f;

    int aRowL = wm * 32 + (lane & 7) + ((lane >> 3) & 1) * 8;   // + mt*16
    int aKbL  = (lane >> 4) * 16;
    int bRowL = wn * 64 + (lane & 7) + (lane >> 4) * 8;         // + nt2*16
    int bKbL  = ((lane >> 3) & 1) * 16;

#pragma unroll
    for (int ks = 0; ks < 16; ks++) {
        int kb = ks * 32;
        unsigned a[2][4];
#pragma unroll
        for (int mt = 0; mt < 2; mt++) {
            int r = aRowL + mt * 16;
            int kbyte = kb + aKbL;
            unsigned addr = aBase + r * 512 + ((((kbyte >> 4) ^ (r & 7)) << 4));
            asm volatile(
                "ldmatrix.sync.aligned.m8n8.x4.shared.b16 {%0,%1,%2,%3}, [%4];"
                : "=r"(a[mt][0]), "=r"(a[mt][1]), "=r"(a[mt][2]), "=r"(a[mt][3])
                : "r"(addr));
        }
        unsigned b[8][2];
#pragma unroll
        for (int nt2 = 0; nt2 < 4; nt2++) {
            int r = bRowL + nt2 * 16;
            int kbyte = kb + bKbL;
            unsigned addr = bBase + r * 512 + ((((kbyte >> 4) ^ (r & 7)) << 4));
            unsigned r0, r1, r2, r3;
            asm volatile(
                "ldmatrix.sync.aligned.m8n8.x4.shared.b16 {%0,%1,%2,%3}, [%4];"
                : "=r"(r0), "=r"(r1), "=r"(r2), "=r"(r3)
                : "r"(addr));
            b[nt2 * 2 + 0][0] = r0; b[nt2 * 2 + 0][1] = r1;
            b[nt2 * 2 + 1][0] = r2; b[nt2 * 2 + 1][1] = r3;
        }
#pragma unroll
        for (int mt = 0; mt < 2; mt++)
#pragma unroll
            for (int nt = 0; nt < 8; nt++) {
                asm volatile(
                    "mma.sync.aligned.m16n8k16.row.col.f32.f16.f16.f32 "
                    "{%0,%1,%2,%3}, {%4,%5,%6,%7}, {%8,%9}, {%0,%1,%2,%3};"
                    : "+f"(c[mt][nt][0]), "+f"(c[mt][nt][1]),
                      "+f"(c[mt][nt][2]), "+f"(c[mt][nt][3])
                    : "r"(a[mt][0]), "r"(a[mt][1]), "r"(a[mt][2]), "r"(a[mt][3]),
                      "r"(b[nt][0]), "r"(b[nt][1]));
            }
    }

    // ---- epilogue: fp16 ft store + fused el/er
    int gid = lane >> 2, tig = lane & 3;

    float2 al2[8], ar2[8];
#pragma unroll
    for (int nt = 0; nt < 8; nt++) {
        int col = wn * 64 + nt * 8 + tig * 2;
        al2[nt] = __ldg((const float2*)al + (col >> 1));   // L1-resident
        ar2[nt] = __ldg((const float2*)ar + (col >> 1));
    }

#pragma unroll
    for (int mt = 0; mt < 2; mt++) {
        int r0 = row0 + wm * 32 + mt * 16 + gid;
        int r1 = r0 + 8;
        // per-thread partial logits: head A = nt 0..3, head B = nt 4..7
        float elA0 = 0.f, elB0 = 0.f, erA0 = 0.f, erB0 = 0.f;  // row r0
        float elA1 = 0.f, elB1 = 0.f, erA1 = 0.f, erB1 = 0.f;  // row r1
#pragma unroll
        for (int nt = 0; nt < 8; nt++) {
            int col = wn * 64 + nt * 8 + tig * 2;
            if (r0 < N_NODES) {
                __half2 h = __floats2half2_rn(c[mt][nt][0], c[mt][nt][1]);
                *(__half2*)(g_ft2 + (size_t)r0 * HF + col) = h;
            }
            if (r1 < N_NODES) {
                __half2 h = __floats2half2_rn(c[mt][nt][2], c[mt][nt][3]);
                *(__half2*)(g_ft2 + (size_t)r1 * HF + col) = h;
            }
            float l0 = c[mt][nt][0] * al2[nt].x + c[mt][nt][1] * al2[nt].y;
            float l1 = c[mt][nt][2] * al2[nt].x + c[mt][nt][3] * al2[nt].y;
            float q0 = c[mt][nt][0] * ar2[nt].x + c[mt][nt][1] * ar2[nt].y;
            float q1 = c[mt][nt][2] * ar2[nt].x + c[mt][nt][3] * ar2[nt].y;
            if (nt < 4) { elA0 += l0; elA1 += l1; erA0 += q0; erA1 += q1; }
            else        { elB0 += l0; elB1 += l1; erB0 += q0; erB1 += q1; }
        }
        // reduce over the 4-lane quad (tig): lanes gid*4+tig
#pragma unroll
        for (int o = 1; o <= 2; o <<= 1) {
            elA0 += __shfl_xor_sync(0xffffffffu, elA0, o);
            elB0 += __shfl_xor_sync(0xffffffffu, elB0, o);
            erA0 += __shfl_xor_sync(0xffffffffu, erA0, o);
            erB0 += __shfl_xor_sync(0xffffffffu, erB0, o);
            elA1 += __shfl_xor_sync(0xffffffffu, elA1, o);
            elB1 += __shfl_xor_sync(0xffffffffu, elB1, o);
            erA1 += __shfl_xor_sync(0xffffffffu, erA1, o);
            erB1 += __shfl_xor_sync(0xffffffffu, erB1, o);
        }
        if (tig == 0) {
            int hA = wn * 2, hB = wn * 2 + 1;
            if (r0 < N_NODES) {
                g_elf[r0 * 4 + hA] = elA0;  g_elf[r0 * 4 + hB] = elB0;
                g_erf[r0 * 4 + hA] = erA0;  g_erf[r0 * 4 + hB] = erB0;
            }
            if (r1 < N_NODES) {
                g_elf[r1 * 4 + hA] = elA1;  g_elf[r1 * 4 + hB] = elB1;
                g_erf[r1 * 4 + hA] = erA1;  g_erf[r1 * 4 + hB] = erB1;
            }
        }
    }
}

// ---------------- 3. histogram of dst ----------------
__global__ void hist_kernel(const int* __restrict__ dst) {
    int i = blockIdx.x * blockDim.x + threadIdx.x;
    if (i < N_EDGES) atomicAdd(&g_counts[dst[i]], 1);
}

// ---------------- 4. two-level exclusive scan ----------------
__global__ void scanA_kernel() {
    __shared__ int sm[SCAN_BLK];
    int t = threadIdx.x;
    int i = blockIdx.x * SCAN_BLK + t;
    int v = (i < N_NODES) ? g_counts[i] : 0;
    sm[t] = v; __syncthreads();
    for (int off = 1; off < SCAN_BLK; off <<= 1) {
        int u = (t >= off) ? sm[t - off] : 0;
        __syncthreads();
        sm[t] += u;
        __syncthreads();
    }
    if (i < N_NODES) g_offsets[i] = sm[t] - v;
    if (t == SCAN_BLK - 1) g_bsums[blockIdx.x] = sm[t];
}

__global__ void __launch_bounds__(512) scanB_kernel() {
    __shared__ int sm[512];
    int t = threadIdx.x;
    int v = (t < N_SCAN_BLOCKS) ? g_bsums[t] : 0;
    sm[t] = v; __syncthreads();
    for (int off = 1; off < 512; off <<= 1) {
        int u = (t >= off) ? sm[t - off] : 0;
        __syncthreads();
        sm[t] += u;
        __syncthreads();
    }
    if (t < N_SCAN_BLOCKS) g_bsums[t] = sm[t] - v;
}

__global__ void scanC_kernel() {
    int i = blockIdx.x * blockDim.x + threadIdx.x;
    if (i < N_NODES) g_offsets[i] += g_bsums[i >> 8];
}

// ---------------- 5. scatter + fused edge softmax weights ----------------
__global__ void scatter_kernel(const int* __restrict__ src,
                               const int* __restrict__ dst) {
    int i = blockIdx.x * blockDim.x + threadIdx.x;
    if (i >= N_EDGES) return;
    int s = src[i];
    int d = dst[i];
    int pos = g_offsets[d] + atomicAdd(&g_cursor[d], 1);
    g_src_sorted[pos] = s;

    float4 el = __ldg(&((const float4*)g_elf)[s]);
    float4 er = __ldg(&((const float4*)g_erf)[d]);
    float t0 = el.x + er.x; t0 = (t0 > 0.f) ? t0 : NEG_SLOPE * t0;
    float t1 = el.y + er.y; t1 = (t1 > 0.f) ? t1 : NEG_SLOPE * t1;
    float t2 = el.z + er.z; t2 = (t2 > 0.f) ? t2 : NEG_SLOPE * t2;
    float t3 = el.w + er.w; t3 = (t3 > 0.f) ? t3 : NEG_SLOPE * t3;
    g_w4[pos] = make_float4(__expf(t0), __expf(t1), __expf(t2), __expf(t3));
}

// ---------------- 6. aggregate: warp/node, 2-wide software pipeline ----------
__global__ void __launch_bounds__(256) agg_kernel(float* __restrict__ out) {
    int n    = (blockIdx.x * blockDim.x + threadIdx.x) >> 5;
    int lane = threadIdx.x & 31;
    if (n >= N_NODES) return;
    int h = lane >> 3;

    int base = __ldg(&g_offsets[n]);
    int deg  = __ldg(&g_counts[n]);

    const float* wh  = ((const float*)g_w4) + h;
    const uint2* ftu = (const uint2*)g_ft2;

    float a0 = 0.f, a1 = 0.f, a2 = 0.f, a3 = 0.f;
    float d = 0.f;

    int s0 = 0, s1 = 0;
    float w0 = 0.f, w1 = 0.f;
    if (deg > 0) { s0 = __ldg(&g_src_sorted[base]);     w0 = __ldg(wh + (size_t)base * 4); }
    if (deg > 1) { s1 = __ldg(&g_src_sorted[base + 1]); w1 = __ldg(wh + (size_t)(base + 1) * 4); }

    for (int j = 0; j < deg; j += 2) {
        bool vB = (j + 1 < deg);
        int   sA = s0,           sB = vB ? s1 : 0;
        float wA = w0,           wB = vB ? w1 : 0.f;
        int jn = j + 2;
        if (jn < deg) {                       // prefetch next pair (padded arrays)
            s0 = __ldg(&g_src_sorted[base + jn]);
            w0 = __ldg(wh + (size_t)(base + jn) * 4);
            s1 = __ldg(&g_src_sorted[base + jn + 1]);
            w1 = __ldg(wh + (size_t)(base + jn + 1) * 4);
        }
        uint2 va = __ldg(&ftu[(size_t)sA * 32 + lane]);   // 2 gathers in flight
        uint2 vb = __ldg(&ftu[(size_t)sB * 32 + lane]);
        float2 fa01 = __half22float2(*(const __half2*)&va.x);
        float2 fa23 = __half22float2(*(const __half2*)&va.y);
        float2 fb01 = __half22float2(*(const __half2*)&vb.x);
        float2 fb23 = __half22float2(*(const __half2*)&vb.y);
        d  += wA + wB;
        a0 += wA * fa01.x + wB * fb01.x;
        a1 += wA * fa01.y + wB * fb01.y;
        a2 += wA * fa23.x + wB * fb23.x;
        a3 += wA * fa23.y + wB * fb23.y;
    }

    float inv = (deg > 0) ? 1.f / d : 0.f;
    float4 o = make_float4(a0 * inv, a1 * inv, a2 * inv, a3 * inv);
    ((float4*)out)[(size_t)n * 32 + lane] = o;
}

// ---------------- launch: fork edge-sort chain onto a second stream ----------
extern "C" void kernel_launch(void* const* d_in, const int* in_sizes, int n_in,
                              void* d_out, int out_size) {
    const float* x    = (const float*)d_in[0];
    const float* fc_w = (const float*)d_in[1];
    const float* al   = (const float*)d_in[2];
    const float* ar   = (const float*)d_in[3];
    const int*   src  = (const int*)d_in[4];
    const int*   dst  = (const int*)d_in[5];
    float*       out  = (float*)d_out;

    static cudaStream_t s2 = nullptr;
    static cudaEvent_t  evF = nullptr, evJ = nullptr;
    if (!s2) {   // first call is the (non-captured) correctness run
        cudaStreamCreateWithFlags(&s2, cudaStreamNonBlocking);
        cudaEventCreateWithFlags(&evF, cudaEventDisableTiming);
        cudaEventCreateWithFlags(&evJ, cudaEventDisableTiming);
        cudaFuncSetAttribute(gemm_kernel,
                             cudaFuncAttributeMaxDynamicSharedMemorySize, 131072);
    }

    // fork
    cudaEventRecord(evF, 0);
    cudaStreamWaitEvent(s2, evF, 0);

    // stream s2: edge-sort chain (needs only dst)
    zero_kernel<<<(N_NODES + 255) / 256, 256, 0, s2>>>();
    hist_kernel<<<(N_EDGES + 255) / 256, 256, 0, s2>>>(dst);
    scanA_kernel<<<N_SCAN_BLOCKS, SCAN_BLK, 0, s2>>>();
    scanB_kernel<<<1, 512, 0, s2>>>();
    scanC_kernel<<<(N_NODES + 255) / 256, 256, 0, s2>>>();
    cudaEventRecord(evJ, s2);

    // stream 0: projection chain (needs only x, W, attn vectors)
    wtrans_kernel<<<(HF * D_IN + 255) / 256, 256>>>(fc_w);
    gemm_kernel<<<GEMM_GRID, 256, 131072>>>(x, al, ar);

    // join, then edge weights + aggregation
    cudaStreamWaitEvent(0, evJ, 0);
    scatter_kernel<<<(N_EDGES + 255) / 256, 256>>>(src, dst);
    agg_kernel<<<(N_NODES * 32) / 256, 256>>>(out);
}

// round 13
// speedup vs baseline: 3.9329x; 1.0663x over previous
#include <cuda_runtime.h>
#include <cuda_fp16.h>

#define N_NODES 100000
#define N_EDGES 1600000
#define D_IN    256
#define HF      128     // N_HEADS * D_OUT
#define NEG_SLOPE 0.2f

#define SCAN_BLK 256
#define N_SCAN_BLOCKS ((N_NODES + SCAN_BLK - 1) / SCAN_BLK)   // 391

#define GEMM_BM 128
#define GEMM_GRID ((N_NODES + GEMM_BM - 1) / GEMM_BM)         // 782

// ---------------- scratch (device globals: allocation-free) ----------------
__device__ __half g_ft2[(size_t)N_NODES * HF];       // 25.6 MB fp16 features
__device__ __half g_wh[HF * D_IN];                   // W fp16, [c][k]
__device__ float  g_elf[N_NODES * 4];
__device__ float  g_erf[N_NODES * 4];
__device__ int    g_counts[N_NODES];
__device__ int    g_offsets[N_NODES];
__device__ int    g_bsums[N_SCAN_BLOCKS];
__device__ int    g_rank[N_EDGES];                   // edge rank within its dst
__device__ int    g_src_sorted[N_EDGES + 4];         // +pad: prefetch overrun safe

// ---------------- 0. zero counters ----------------
__global__ void zero_kernel() {
    int i = blockIdx.x * blockDim.x + threadIdx.x;
    if (i < N_NODES) g_counts[i] = 0;
}

// ---------------- 1. W fp32 -> fp16 ----------------
__global__ void wtrans_kernel(const float* __restrict__ w) {
    int i = blockIdx.x * blockDim.x + threadIdx.x;
    if (i < HF * D_IN) g_wh[i] = __float2half(w[i]);
}

// ---------------- 2. HMMA GEMM + fused el/er epilogue ----------------
// Block 128x128xK256, 8 warps (4m x 2n), warp tile 32x64 = 2x8 m16n8k16.
// Head h = cols [32h,32h+32) lives entirely in warp wn = h>>1: el/er reduce
// with 2 shfl_xor over the 4-lane quad; lane tig==0 stores.
__global__ void __launch_bounds__(256) gemm_kernel(const float* __restrict__ x,
                                                   const float* __restrict__ al,
                                                   const float* __restrict__ ar) {
    extern __shared__ char smem[];
    char* As = smem;            // 65536 bytes
    char* Bs = smem + 65536;    // 65536 bytes

    int tid  = threadIdx.x;
    int lane = tid & 31;
    int wid  = tid >> 5;
    int wm   = wid & 3;
    int wn   = wid >> 2;
    int row0 = blockIdx.x * GEMM_BM;

    // ---- fill A: x fp32 -> fp16, swizzled (16B chunk per thread-iter)
#pragma unroll
    for (int it = 0; it < 16; it++) {
        int cid = tid + 256 * it;
        int row = cid >> 5;
        int ck  = cid & 31;
        int grow = row0 + row;
        float4 f0, f1;
        if (grow < N_NODES) {
            const float4* xp = (const float4*)(x + (size_t)grow * D_IN + ck * 8);
            f0 = __ldg(xp); f1 = __ldg(xp + 1);
        } else {
            f0 = make_float4(0.f, 0.f, 0.f, 0.f); f1 = f0;
        }
        __half2 h0 = __floats2half2_rn(f0.x, f0.y);
        __half2 h1 = __floats2half2_rn(f0.z, f0.w);
        __half2 h2 = __floats2half2_rn(f1.x, f1.y);
        __half2 h3 = __floats2half2_rn(f1.z, f1.w);
        uint4 v = make_uint4(*(unsigned*)&h0, *(unsigned*)&h1,
                             *(unsigned*)&h2, *(unsigned*)&h3);
        *(uint4*)(As + row * 512 + ((ck ^ (row & 7)) << 4)) = v;
    }
    // ---- fill B: g_wh fp16 straight copy, swizzled
#pragma unroll
    for (int it = 0; it < 16; it++) {
        int cid = tid + 256 * it;
        int row = cid >> 5;
        int ck  = cid & 31;
        uint4 v = __ldg((const uint4*)(g_wh + row * D_IN + ck * 8));
        *(uint4*)(Bs + row * 512 + ((ck ^ (row & 7)) << 4)) = v;
    }
    __syncthreads();

    unsigned aBase = (unsigned)__cvta_generic_to_shared(As);
    unsigned bBase = (unsigned)__cvta_generic_to_shared(Bs);

    float c[2][8][4];
#pragma unroll
    for (int mt = 0; mt < 2; mt++)
#pragma unroll
        for (int nt = 0; nt < 8; nt++)
#pragma unroll
            for (int e = 0; e < 4; e++) c[mt][nt][e] = 0.f;

    int aRowL = wm * 32 + (lane & 7) + ((lane >> 3) & 1) * 8;
    int aKbL  = (lane >> 4) * 16;
    int bRowL = wn * 64 + (lane & 7) + (lane >> 4) * 8;
    int bKbL  = ((lane >> 3) & 1) * 16;

#pragma unroll
    for (int ks = 0; ks < 16; ks++) {
        int kb = ks * 32;
        unsigned a[2][4];
#pragma unroll
        for (int mt = 0; mt < 2; mt++) {
            int r = aRowL + mt * 16;
            int kbyte = kb + aKbL;
            unsigned addr = aBase + r * 512 + ((((kbyte >> 4) ^ (r & 7)) << 4));
            asm volatile(
                "ldmatrix.sync.aligned.m8n8.x4.shared.b16 {%0,%1,%2,%3}, [%4];"
                : "=r"(a[mt][0]), "=r"(a[mt][1]), "=r"(a[mt][2]), "=r"(a[mt][3])
                : "r"(addr));
        }
        unsigned b[8][2];
#pragma unroll
        for (int nt2 = 0; nt2 < 4; nt2++) {
            int r = bRowL + nt2 * 16;
            int kbyte = kb + bKbL;
            unsigned addr = bBase + r * 512 + ((((kbyte >> 4) ^ (r & 7)) << 4));
            unsigned r0, r1, r2, r3;
            asm volatile(
                "ldmatrix.sync.aligned.m8n8.x4.shared.b16 {%0,%1,%2,%3}, [%4];"
                : "=r"(r0), "=r"(r1), "=r"(r2), "=r"(r3)
                : "r"(addr));
            b[nt2 * 2 + 0][0] = r0; b[nt2 * 2 + 0][1] = r1;
            b[nt2 * 2 + 1][0] = r2; b[nt2 * 2 + 1][1] = r3;
        }
#pragma unroll
        for (int mt = 0; mt < 2; mt++)
#pragma unroll
            for (int nt = 0; nt < 8; nt++) {
                asm volatile(
                    "mma.sync.aligned.m16n8k16.row.col.f32.f16.f16.f32 "
                    "{%0,%1,%2,%3}, {%4,%5,%6,%7}, {%8,%9}, {%0,%1,%2,%3};"
                    : "+f"(c[mt][nt][0]), "+f"(c[mt][nt][1]),
                      "+f"(c[mt][nt][2]), "+f"(c[mt][nt][3])
                    : "r"(a[mt][0]), "r"(a[mt][1]), "r"(a[mt][2]), "r"(a[mt][3]),
                      "r"(b[nt][0]), "r"(b[nt][1]));
            }
    }

    // ---- epilogue: fp16 ft store + fused el/er
    int gid = lane >> 2, tig = lane & 3;

    float2 al2[8], ar2[8];
#pragma unroll
    for (int nt = 0; nt < 8; nt++) {
        int col = wn * 64 + nt * 8 + tig * 2;
        al2[nt] = __ldg((const float2*)al + (col >> 1));
        ar2[nt] = __ldg((const float2*)ar + (col >> 1));
    }

#pragma unroll
    for (int mt = 0; mt < 2; mt++) {
        int r0 = row0 + wm * 32 + mt * 16 + gid;
        int r1 = r0 + 8;
        float elA0 = 0.f, elB0 = 0.f, erA0 = 0.f, erB0 = 0.f;
        float elA1 = 0.f, elB1 = 0.f, erA1 = 0.f, erB1 = 0.f;
#pragma unroll
        for (int nt = 0; nt < 8; nt++) {
            int col = wn * 64 + nt * 8 + tig * 2;
            if (r0 < N_NODES) {
                __half2 h = __floats2half2_rn(c[mt][nt][0], c[mt][nt][1]);
                *(__half2*)(g_ft2 + (size_t)r0 * HF + col) = h;
            }
            if (r1 < N_NODES) {
                __half2 h = __floats2half2_rn(c[mt][nt][2], c[mt][nt][3]);
                *(__half2*)(g_ft2 + (size_t)r1 * HF + col) = h;
            }
            float l0 = c[mt][nt][0] * al2[nt].x + c[mt][nt][1] * al2[nt].y;
            float l1 = c[mt][nt][2] * al2[nt].x + c[mt][nt][3] * al2[nt].y;
            float q0 = c[mt][nt][0] * ar2[nt].x + c[mt][nt][1] * ar2[nt].y;
            float q1 = c[mt][nt][2] * ar2[nt].x + c[mt][nt][3] * ar2[nt].y;
            if (nt < 4) { elA0 += l0; elA1 += l1; erA0 += q0; erA1 += q1; }
            else        { elB0 += l0; elB1 += l1; erB0 += q0; erB1 += q1; }
        }
#pragma unroll
        for (int o = 1; o <= 2; o <<= 1) {
            elA0 += __shfl_xor_sync(0xffffffffu, elA0, o);
            elB0 += __shfl_xor_sync(0xffffffffu, elB0, o);
            erA0 += __shfl_xor_sync(0xffffffffu, erA0, o);
            erB0 += __shfl_xor_sync(0xffffffffu, erB0, o);
            elA1 += __shfl_xor_sync(0xffffffffu, elA1, o);
            elB1 += __shfl_xor_sync(0xffffffffu, elB1, o);
            erA1 += __shfl_xor_sync(0xffffffffu, erA1, o);
            erB1 += __shfl_xor_sync(0xffffffffu, erB1, o);
        }
        if (tig == 0) {
            int hA = wn * 2, hB = wn * 2 + 1;
            if (r0 < N_NODES) {
                g_elf[r0 * 4 + hA] = elA0;  g_elf[r0 * 4 + hB] = elB0;
                g_erf[r0 * 4 + hA] = erA0;  g_erf[r0 * 4 + hB] = erB0;
            }
            if (r1 < N_NODES) {
                g_elf[r1 * 4 + hA] = elA1;  g_elf[r1 * 4 + hB] = elB1;
                g_erf[r1 * 4 + hA] = erA1;  g_erf[r1 * 4 + hB] = erB1;
            }
        }
    }
}

// ---------------- 3. histogram of dst + per-edge rank ----------------
__global__ void hist_kernel(const int* __restrict__ dst) {
    int i = blockIdx.x * blockDim.x + threadIdx.x;
    if (i < N_EDGES) g_rank[i] = atomicAdd(&g_counts[dst[i]], 1);
}

// ---------------- 4. two-level exclusive scan ----------------
__global__ void scanA_kernel() {
    __shared__ int sm[SCAN_BLK];
    int t = threadIdx.x;
    int i = blockIdx.x * SCAN_BLK + t;
    int v = (i < N_NODES) ? g_counts[i] : 0;
    sm[t] = v; __syncthreads();
    for (int off = 1; off < SCAN_BLK; off <<= 1) {
        int u = (t >= off) ? sm[t - off] : 0;
        __syncthreads();
        sm[t] += u;
        __syncthreads();
    }
    if (i < N_NODES) g_offsets[i] = sm[t] - v;
    if (t == SCAN_BLK - 1) g_bsums[blockIdx.x] = sm[t];
}

__global__ void __launch_bounds__(512) scanB_kernel() {
    __shared__ int sm[512];
    int t = threadIdx.x;
    int v = (t < N_SCAN_BLOCKS) ? g_bsums[t] : 0;
    sm[t] = v; __syncthreads();
    for (int off = 1; off < 512; off <<= 1) {
        int u = (t >= off) ? sm[t - off] : 0;
        __syncthreads();
        sm[t] += u;
        __syncthreads();
    }
    if (t < N_SCAN_BLOCKS) g_bsums[t] = sm[t] - v;
}

__global__ void scanC_kernel() {
    int i = blockIdx.x * blockDim.x + threadIdx.x;
    if (i < N_NODES) g_offsets[i] += g_bsums[i >> 8];
}

// ---------------- 5. scatter src into dst-sorted order (atomic-free, ---------
// gemm-independent: runs in the edge stream, parallel with the GEMM) ----------
__global__ void scatter_kernel(const int* __restrict__ src,
                               const int* __restrict__ dst) {
    int i = blockIdx.x * blockDim.x + threadIdx.x;
    if (i >= N_EDGES) return;
    int d = dst[i];
    g_src_sorted[g_offsets[d] + g_rank[i]] = src[i];
}

// ---------------- 6. aggregate: warp/node, inline softmax weights ------------
// Lane owns head h = lane>>3. Per edge: broadcast 4B src load, 4B el[s][h]
// load (4 addrs in one line), 8B fp16 ft gather, 1 exp. Denominator needs no
// reduction (8 lanes of a head accumulate identical sums). 2-wide pipeline.
__global__ void __launch_bounds__(256) agg_kernel(float* __restrict__ out) {
    int n    = (blockIdx.x * blockDim.x + threadIdx.x) >> 5;
    int lane = threadIdx.x & 31;
    if (n >= N_NODES) return;
    int h = lane >> 3;

    int base = __ldg(&g_offsets[n]);
    int deg  = __ldg(&g_counts[n]);

    float erh = __ldg(&g_erf[n * 4 + h]);
    const float* elf = g_elf;
    const uint2* ftu = (const uint2*)g_ft2;

    float a0 = 0.f, a1 = 0.f, a2 = 0.f, a3 = 0.f;
    float d = 0.f;

    int s0 = 0, s1 = 0;
    if (deg > 0) s0 = __ldg(&g_src_sorted[base]);
    if (deg > 1) s1 = __ldg(&g_src_sorted[base + 1]);

    for (int j = 0; j < deg; j += 2) {
        bool vB = (j + 1 < deg);
        int sA = s0, sB = s1;
        int jn = j + 2;
        if (jn < deg) {                      // prefetch next pair (padded array)
            s0 = __ldg(&g_src_sorted[base + jn]);
            s1 = __ldg(&g_src_sorted[base + jn + 1]);
        }
        float eA = __ldg(elf + sA * 4 + h);              // 1 wavefront
        float eB = __ldg(elf + sB * 4 + h);
        uint2 va = __ldg(&ftu[(size_t)sA * 32 + lane]);  // 2 gathers in flight
        uint2 vb = __ldg(&ftu[(size_t)sB * 32 + lane]);

        float tA = eA + erh; tA = (tA > 0.f) ? tA : NEG_SLOPE * tA;
        float tB = eB + erh; tB = (tB > 0.f) ? tB : NEG_SLOPE * tB;
        float wA = __expf(tA);
        float wB = vB ? __expf(tB) : 0.f;

        float2 fa01 = __half22float2(*(const __half2*)&va.x);
        float2 fa23 = __half22float2(*(const __half2*)&va.y);
        float2 fb01 = __half22float2(*(const __half2*)&vb.x);
        float2 fb23 = __half22float2(*(const __half2*)&vb.y);
        d  += wA + wB;
        a0 += wA * fa01.x + wB * fb01.x;
        a1 += wA * fa01.y + wB * fb01.y;
        a2 += wA * fa23.x + wB * fb23.x;
        a3 += wA * fa23.y + wB * fb23.y;
    }

    float inv = (deg > 0) ? 1.f / d : 0.f;
    float4 o = make_float4(a0 * inv, a1 * inv, a2 * inv, a3 * inv);
    ((float4*)out)[(size_t)n * 32 + lane] = o;
}

// ---------------- launch: edge-sort chain fully parallel with GEMM ----------
extern "C" void kernel_launch(void* const* d_in, const int* in_sizes, int n_in,
                              void* d_out, int out_size) {
    const float* x    = (const float*)d_in[0];
    const float* fc_w = (const float*)d_in[1];
    const float* al   = (const float*)d_in[2];
    const float* ar   = (const float*)d_in[3];
    const int*   src  = (const int*)d_in[4];
    const int*   dst  = (const int*)d_in[5];
    float*       out  = (float*)d_out;

    static cudaStream_t s2 = nullptr;
    static cudaEvent_t  evF = nullptr, evJ = nullptr;
    if (!s2) {   // first call is the (non-captured) correctness run
        cudaStreamCreateWithFlags(&s2, cudaStreamNonBlocking);
        cudaEventCreateWithFlags(&evF, cudaEventDisableTiming);
        cudaEventCreateWithFlags(&evJ, cudaEventDisableTiming);
        cudaFuncSetAttribute(gemm_kernel,
                             cudaFuncAttributeMaxDynamicSharedMemorySize, 131072);
    }

    // fork
    cudaEventRecord(evF, 0);
    cudaStreamWaitEvent(s2, evF, 0);

    // stream s2: full edge-sort chain (zero -> hist+rank -> scan -> scatter)
    zero_kernel<<<(N_NODES + 255) / 256, 256, 0, s2>>>();
    hist_kernel<<<(N_EDGES + 255) / 256, 256, 0, s2>>>(dst);
    scanA_kernel<<<N_SCAN_BLOCKS, SCAN_BLK, 0, s2>>>();
    scanB_kernel<<<1, 512, 0, s2>>>();
    scanC_kernel<<<(N_NODES + 255) / 256, 256, 0, s2>>>();
    scatter_kernel<<<(N_EDGES + 255) / 256, 256, 0, s2>>>(src, dst);
    cudaEventRecord(evJ, s2);

    // stream 0: projection chain
    wtrans_kernel<<<(HF * D_IN + 255) / 256, 256>>>(fc_w);
    gemm_kernel<<<GEMM_GRID, 256, 131072>>>(x, al, ar);

    // join, then aggregation (weights computed inline)
    cudaStreamWaitEvent(0, evJ, 0);
    agg_kernel<<<(N_NODES * 32) / 256, 256>>>(out);
}

// round 15
// speedup vs baseline: 4.1680x; 1.0598x over previous
#include <cuda_runtime.h>
#include <cuda_fp16.h>

#define N_NODES 100000
#define N_EDGES 1600000
#define D_IN    256
#define HF      128     // N_HEADS * D_OUT
#define NEG_SLOPE 0.2f

#define SCAN_BLK 256
#define N_SCAN_BLOCKS ((N_NODES + SCAN_BLK - 1) / SCAN_BLK)   // 391

#define GEMM_BM 128
#define GEMM_GRID ((N_NODES + GEMM_BM - 1) / GEMM_BM)         // 782

// ---------------- scratch (device globals: allocation-free) ----------------
__device__ __half g_ft2[(size_t)N_NODES * HF];       // 25.6 MB fp16 features
__device__ __half g_wh[HF * D_IN];                   // W fp16, [c][k]
__device__ float  g_elf[N_NODES * 4];
__device__ float  g_erf[N_NODES * 4];
__device__ int    g_counts[N_NODES];
__device__ int    g_offsets[N_NODES];
__device__ unsigned long long g_scan_state[N_SCAN_BLOCKS];  // flag<<32 | value
__device__ int    g_rank[N_EDGES];                   // edge rank within its dst
__device__ int    g_src_sorted[N_EDGES + 4];         // +pad: prefetch overrun safe

// ---------------- 0. zero counters + scan state ----------------
__global__ void zero_kernel() {
    int i = blockIdx.x * blockDim.x + threadIdx.x;
    if (i < N_NODES) g_counts[i] = 0;
    if (i < N_SCAN_BLOCKS) g_scan_state[i] = 0ULL;
}

// ---------------- 1. W fp32 -> fp16 ----------------
__global__ void wtrans_kernel(const float* __restrict__ w) {
    int i = blockIdx.x * blockDim.x + threadIdx.x;
    if (i < HF * D_IN) g_wh[i] = __float2half(w[i]);
}

// ---------------- 2. HMMA GEMM + fused el/er epilogue ----------------
// Block 128x128xK256, 8 warps (4m x 2n), warp tile 32x64 = 2x8 m16n8k16.
__global__ void __launch_bounds__(256) gemm_kernel(const float* __restrict__ x,
                                                   const float* __restrict__ al,
                                                   const float* __restrict__ ar) {
    extern __shared__ char smem[];
    char* As = smem;            // 65536 bytes
    char* Bs = smem + 65536;    // 65536 bytes

    int tid  = threadIdx.x;
    int lane = tid & 31;
    int wid  = tid >> 5;
    int wm   = wid & 3;
    int wn   = wid >> 2;
    int row0 = blockIdx.x * GEMM_BM;

#pragma unroll
    for (int it = 0; it < 16; it++) {
        int cid = tid + 256 * it;
        int row = cid >> 5;
        int ck  = cid & 31;
        int grow = row0 + row;
        float4 f0, f1;
        if (grow < N_NODES) {
            const float4* xp = (const float4*)(x + (size_t)grow * D_IN + ck * 8);
            f0 = __ldg(xp); f1 = __ldg(xp + 1);
        } else {
            f0 = make_float4(0.f, 0.f, 0.f, 0.f); f1 = f0;
        }
        __half2 h0 = __floats2half2_rn(f0.x, f0.y);
        __half2 h1 = __floats2half2_rn(f0.z, f0.w);
        __half2 h2 = __floats2half2_rn(f1.x, f1.y);
        __half2 h3 = __floats2half2_rn(f1.z, f1.w);
        uint4 v = make_uint4(*(unsigned*)&h0, *(unsigned*)&h1,
                             *(unsigned*)&h2, *(unsigned*)&h3);
        *(uint4*)(As + row * 512 + ((ck ^ (row & 7)) << 4)) = v;
    }
#pragma unroll
    for (int it = 0; it < 16; it++) {
        int cid = tid + 256 * it;
        int row = cid >> 5;
        int ck  = cid & 31;
        uint4 v = __ldg((const uint4*)(g_wh + row * D_IN + ck * 8));
        *(uint4*)(Bs + row * 512 + ((ck ^ (row & 7)) << 4)) = v;
    }
    __syncthreads();

    unsigned aBase = (unsigned)__cvta_generic_to_shared(As);
    unsigned bBase = (unsigned)__cvta_generic_to_shared(Bs);

    float c[2][8][4];
#pragma unroll
    for (int mt = 0; mt < 2; mt++)
#pragma unroll
        for (int nt = 0; nt < 8; nt++)
#pragma unroll
            for (int e = 0; e < 4; e++) c[mt][nt][e] = 0.f;

    int aRowL = wm * 32 + (lane & 7) + ((lane >> 3) & 1) * 8;
    int aKbL  = (lane >> 4) * 16;
    int bRowL = wn * 64 + (lane & 7) + (lane >> 4) * 8;
    int bKbL  = ((lane >> 3) & 1) * 16;

#pragma unroll
    for (int ks = 0; ks < 16; ks++) {
        int kb = ks * 32;
        unsigned a[2][4];
#pragma unroll
        for (int mt = 0; mt < 2; mt++) {
            int r = aRowL + mt * 16;
            int kbyte = kb + aKbL;
            unsigned addr = aBase + r * 512 + ((((kbyte >> 4) ^ (r & 7)) << 4));
            asm volatile(
                "ldmatrix.sync.aligned.m8n8.x4.shared.b16 {%0,%1,%2,%3}, [%4];"
                : "=r"(a[mt][0]), "=r"(a[mt][1]), "=r"(a[mt][2]), "=r"(a[mt][3])
                : "r"(addr));
        }
        unsigned b[8][2];
#pragma unroll
        for (int nt2 = 0; nt2 < 4; nt2++) {
            int r = bRowL + nt2 * 16;
            int kbyte = kb + bKbL;
            unsigned addr = bBase + r * 512 + ((((kbyte >> 4) ^ (r & 7)) << 4));
            unsigned r0, r1, r2, r3;
            asm volatile(
                "ldmatrix.sync.aligned.m8n8.x4.shared.b16 {%0,%1,%2,%3}, [%4];"
                : "=r"(r0), "=r"(r1), "=r"(r2), "=r"(r3)
                : "r"(addr));
            b[nt2 * 2 + 0][0] = r0; b[nt2 * 2 + 0][1] = r1;
            b[nt2 * 2 + 1][0] = r2; b[nt2 * 2 + 1][1] = r3;
        }
#pragma unroll
        for (int mt = 0; mt < 2; mt++)
#pragma unroll
            for (int nt = 0; nt < 8; nt++) {
                asm volatile(
                    "mma.sync.aligned.m16n8k16.row.col.f32.f16.f16.f32 "
                    "{%0,%1,%2,%3}, {%4,%5,%6,%7}, {%8,%9}, {%0,%1,%2,%3};"
                    : "+f"(c[mt][nt][0]), "+f"(c[mt][nt][1]),
                      "+f"(c[mt][nt][2]), "+f"(c[mt][nt][3])
                    : "r"(a[mt][0]), "r"(a[mt][1]), "r"(a[mt][2]), "r"(a[mt][3]),
                      "r"(b[nt][0]), "r"(b[nt][1]));
            }
    }

    int gid = lane >> 2, tig = lane & 3;

    float2 al2[8], ar2[8];
#pragma unroll
    for (int nt = 0; nt < 8; nt++) {
        int col = wn * 64 + nt * 8 + tig * 2;
        al2[nt] = __ldg((const float2*)al + (col >> 1));
        ar2[nt] = __ldg((const float2*)ar + (col >> 1));
    }

#pragma unroll
    for (int mt = 0; mt < 2; mt++) {
        int r0 = row0 + wm * 32 + mt * 16 + gid;
        int r1 = r0 + 8;
        float elA0 = 0.f, elB0 = 0.f, erA0 = 0.f, erB0 = 0.f;
        float elA1 = 0.f, elB1 = 0.f, erA1 = 0.f, erB1 = 0.f;
#pragma unroll
        for (int nt = 0; nt < 8; nt++) {
            int col = wn * 64 + nt * 8 + tig * 2;
            if (r0 < N_NODES) {
                __half2 h = __floats2half2_rn(c[mt][nt][0], c[mt][nt][1]);
                *(__half2*)(g_ft2 + (size_t)r0 * HF + col) = h;
            }
            if (r1 < N_NODES) {
                __half2 h = __floats2half2_rn(c[mt][nt][2], c[mt][nt][3]);
                *(__half2*)(g_ft2 + (size_t)r1 * HF + col) = h;
            }
            float l0 = c[mt][nt][0] * al2[nt].x + c[mt][nt][1] * al2[nt].y;
            float l1 = c[mt][nt][2] * al2[nt].x + c[mt][nt][3] * al2[nt].y;
            float q0 = c[mt][nt][0] * ar2[nt].x + c[mt][nt][1] * ar2[nt].y;
            float q1 = c[mt][nt][2] * ar2[nt].x + c[mt][nt][3] * ar2[nt].y;
            if (nt < 4) { elA0 += l0; elA1 += l1; erA0 += q0; erA1 += q1; }
            else        { elB0 += l0; elB1 += l1; erB0 += q0; erB1 += q1; }
        }
#pragma unroll
        for (int o = 1; o <= 2; o <<= 1) {
            elA0 += __shfl_xor_sync(0xffffffffu, elA0, o);
            elB0 += __shfl_xor_sync(0xffffffffu, elB0, o);
            erA0 += __shfl_xor_sync(0xffffffffu, erA0, o);
            erB0 += __shfl_xor_sync(0xffffffffu, erB0, o);
            elA1 += __shfl_xor_sync(0xffffffffu, elA1, o);
            elB1 += __shfl_xor_sync(0xffffffffu, elB1, o);
            erA1 += __shfl_xor_sync(0xffffffffu, erA1, o);
            erB1 += __shfl_xor_sync(0xffffffffu, erB1, o);
        }
        if (tig == 0) {
            int hA = wn * 2, hB = wn * 2 + 1;
            if (r0 < N_NODES) {
                g_elf[r0 * 4 + hA] = elA0;  g_elf[r0 * 4 + hB] = elB0;
                g_erf[r0 * 4 + hA] = erA0;  g_erf[r0 * 4 + hB] = erB0;
            }
            if (r1 < N_NODES) {
                g_elf[r1 * 4 + hA] = elA1;  g_elf[r1 * 4 + hB] = elB1;
                g_erf[r1 * 4 + hA] = erA1;  g_erf[r1 * 4 + hB] = erB1;
            }
        }
    }
}

// ---------------- 3. histogram of dst + per-edge rank ----------------
__global__ void hist_kernel(const int* __restrict__ dst) {
    int i = blockIdx.x * blockDim.x + threadIdx.x;
    if (i < N_EDGES) g_rank[i] = atomicAdd(&g_counts[dst[i]], 1);
}

// ---------------- 4. single-pass exclusive scan (decoupled lookback) --------
// flag (bits 32+): 0 = invalid, 1 = aggregate ready, 2 = inclusive ready.
// Values are deterministic; spinning only affects timing.
__global__ void __launch_bounds__(SCAN_BLK) scan_kernel() {
    __shared__ int warp_sums[8];
    __shared__ int s_prefix;
    int t = threadIdx.x, b = blockIdx.x;
    int i = b * SCAN_BLK + t;
    int lane = t & 31, w = t >> 5;

    int v = (i < N_NODES) ? g_counts[i] : 0;
    int xi = v;
#pragma unroll
    for (int o = 1; o < 32; o <<= 1) {
        int u = __shfl_up_sync(0xffffffffu, xi, o);
        if (lane >= o) xi += u;
    }
    if (lane == 31) warp_sums[w] = xi;
    __syncthreads();
    if (w == 0) {
        int s = (lane < 8) ? warp_sums[lane] : 0;
#pragma unroll
        for (int o = 1; o < 8; o <<= 1) {
            int u = __shfl_up_sync(0xffffffffu, s, o);
            if (lane >= o) s += u;
        }
        if (lane < 8) warp_sums[lane] = s;
    }
    __syncthreads();
    int excl = xi - v + ((w > 0) ? warp_sums[w - 1] : 0);
    int block_total = warp_sums[7];

    if (t == 0) {
        if (b == 0) {
            atomicExch(&g_scan_state[0],
                       (2ULL << 32) | (unsigned)block_total);
            s_prefix = 0;
        } else {
            atomicExch(&g_scan_state[b],
                       (1ULL << 32) | (unsigned)block_total);
            int running = 0;
            int p = b - 1;
            while (true) {
                unsigned long long st = atomicAdd(&g_scan_state[p], 0ULL);
                unsigned f = (unsigned)(st >> 32);
                if (f == 2u) { running += (int)(unsigned)st; break; }
                if (f == 1u) { running += (int)(unsigned)st; p--; }
            }
            atomicExch(&g_scan_state[b],
                       (2ULL << 32) | (unsigned)(block_total + running));
            s_prefix = running;
        }
    }
    __syncthreads();
    if (i < N_NODES) g_offsets[i] = excl + s_prefix;
}

// ---------------- 5. scatter src into dst-sorted order (atomic-free) --------
__global__ void scatter_kernel(const int* __restrict__ src,
                               const int* __restrict__ dst) {
    int i = blockIdx.x * blockDim.x + threadIdx.x;
    if (i >= N_EDGES) return;
    int d = dst[i];
    g_src_sorted[g_offsets[d] + g_rank[i]] = src[i];
}

// ---------------- 6. aggregate: warp/node, half-warp per edge ----------------
// Lanes 0-15 process edge A, lanes 16-31 edge B. Lane q=lane&15 owns one 16B
// chunk (elements 8q..8q+7, head q>>2). Per edge-pair: 1 LDG.128 (ft), 1 LDG
// (el), 2 prefetch LDG (src), 1 MUFU. Halves combined once at the end.
__global__ void __launch_bounds__(256) agg_kernel(float* __restrict__ out) {
    int n    = (blockIdx.x * blockDim.x + threadIdx.x) >> 5;
    int lane = threadIdx.x & 31;
    if (n >= N_NODES) return;
    int q    = lane & 15;
    int hq   = q >> 2;
    int half = lane >> 4;

    int base = __ldg(&g_offsets[n]);
    int deg  = __ldg(&g_counts[n]);
    float erh = __ldg(&g_erf[n * 4 + hq]);

    const uint4* ft16 = (const uint4*)g_ft2;   // 16 chunks per 256B row
    const float* elf  = g_elf;

    float a[8];
#pragma unroll
    for (int k = 0; k < 8; k++) a[k] = 0.f;
    float d = 0.f;

    int s0 = 0, s1 = 0;
    if (deg > 0) s0 = __ldg(&g_src_sorted[base]);
    if (deg > 1) s1 = __ldg(&g_src_sorted[base + 1]);

    for (int j = 0; j < deg; j += 2) {
        int  sA = s0, sB = s1;
        bool vB = (j + 1 < deg);
        int jn = j + 2;
        if (jn < deg) {                      // prefetch next pair (padded array)
            s0 = __ldg(&g_src_sorted[base + jn]);
            s1 = __ldg(&g_src_sorted[base + jn + 1]);
        }
        int  s     = half ? sB : sA;
        bool valid = half ? vB : true;
        float e = __ldg(elf + s * 4 + hq);
        uint4 v = __ldg(&ft16[(size_t)s * 16 + q]);      // warp: 2 rows x 256B
        float t = e + erh; t = (t > 0.f) ? t : NEG_SLOPE * t;
        float w = valid ? __expf(t) : 0.f;
        d += w;
        const __half2* hv = (const __half2*)&v;
#pragma unroll
        for (int k = 0; k < 4; k++) {
            float2 f = __half22float2(hv[k]);
            a[2 * k]     += w * f.x;
            a[2 * k + 1] += w * f.y;
        }
    }

    // combine the two halves
    d += __shfl_xor_sync(0xffffffffu, d, 16);
#pragma unroll
    for (int k = 0; k < 8; k++) a[k] += __shfl_xor_sync(0xffffffffu, a[k], 16);

    float inv = (deg > 0) ? 1.f / d : 0.f;
    if (lane < 16) {
        float4 o0 = make_float4(a[0] * inv, a[1] * inv, a[2] * inv, a[3] * inv);
        float4 o1 = make_float4(a[4] * inv, a[5] * inv, a[6] * inv, a[7] * inv);
        float4* op = (float4*)out + (size_t)n * 32 + q * 2;
        op[0] = o0;
        op[1] = o1;
    }
}

// ---------------- launch: edge-sort chain fully parallel with GEMM ----------
extern "C" void kernel_launch(void* const* d_in, const int* in_sizes, int n_in,
                              void* d_out, int out_size) {
    const float* x    = (const float*)d_in[0];
    const float* fc_w = (const float*)d_in[1];
    const float* al   = (const float*)d_in[2];
    const float* ar   = (const float*)d_in[3];
    const int*   src  = (const int*)d_in[4];
    const int*   dst  = (const int*)d_in[5];
    float*       out  = (float*)d_out;

    static cudaStream_t s2 = nullptr;
    static cudaEvent_t  evF = nullptr, evJ = nullptr;
    if (!s2) {   // first call is the (non-captured) correctness run
        cudaStreamCreateWithFlags(&s2, cudaStreamNonBlocking);
        cudaEventCreateWithFlags(&evF, cudaEventDisableTiming);
        cudaEventCreateWithFlags(&evJ, cudaEventDisableTiming);
        cudaFuncSetAttribute(gemm_kernel,
                             cudaFuncAttributeMaxDynamicSharedMemorySize, 131072);
    }

    // fork
    cudaEventRecord(evF, 0);
    cudaStreamWaitEvent(s2, evF, 0);

    // stream s2: full edge-sort chain
    zero_kernel<<<(N_NODES + 255) / 256, 256, 0, s2>>>();
    hist_kernel<<<(N_EDGES + 255) / 256, 256, 0, s2>>>(dst);
    scan_kernel<<<N_SCAN_BLOCKS, SCAN_BLK, 0, s2>>>();
    scatter_kernel<<<(N_EDGES + 255) / 256, 256, 0, s2>>>(src, dst);
    cudaEventRecord(evJ, s2);

    // stream 0: projection chain
    wtrans_kernel<<<(HF * D_IN + 255) / 256, 256>>>(fc_w);
    gemm_kernel<<<GEMM_GRID, 256, 131072>>>(x, al, ar);

    // join, then aggregation (weights computed inline)
    cudaStreamWaitEvent(0, evJ, 0);
    agg_kernel<<<(N_NODES * 32) / 256, 256>>>(out);
}